// round 6
// baseline (speedup 1.0000x reference)
#include <cuda_runtime.h>
#include <cstdint>

#define N_NODES   200000
#define N_CHILD   32
#define N_LAYERS  8
#define CLUSTER   4
#define CHUNK     50000          // floats per CTA: 200KB smem; 4*50000 = 200000
#define THREADS   1024
#define RANGE     1352           // 148*1352 = 200096 >= 200000; multiple of 8

// Ping-pong layer-value buffers (no runtime allocation allowed).
// NOTE: src and dst MUST be distinct arrays — there is no grid-wide sync
// inside a launch, so writing the array being staged races across clusters
// (this exact bug caused the R5 failure).
__device__ float g_bufA[N_NODES];
__device__ float g_bufB[N_NODES];

// One cluster of 4 CTAs holds the entire 800KB previous-layer array in
// distributed shared memory. CTA with cluster rank r stages src[r*50000 ..
// +50000). After cluster.sync, each CTA processes its own node range; every
// child gather is an ld.shared::cluster into the owning CTA's smem.
// Warp layout: 8 nodes/warp-task via 2 int4 index loads/lane; 8-lane shfl
// groups reduce each node; activation applied inline -> single pass, no
// partials, indices read exactly once.
__global__ void __launch_bounds__(THREADS, 1) layer_cluster_kernel(
    const float* __restrict__ src,     // previous layer values [N_NODES]
    float*       __restrict__ dst,     // this layer's outputs   [N_NODES]
    const int4*  __restrict__ cidx,    // this layer's indices as int4
    const int*   __restrict__ fids,    // this layer's fun_ids
    const float* __restrict__ wptr)
{
    extern __shared__ float sval[];    // CHUNK floats

    uint32_t rank;
    asm("mov.u32 %0, %%cluster_ctarank;" : "=r"(rank));

    // Stage this CTA's chunk (coalesced float4; src is L2-resident).
    {
        const float4* s4 = (const float4*)(src + (size_t)rank * CHUNK);
        float4* d4 = (float4*)sval;
        for (int i = threadIdx.x; i < CHUNK / 4; i += THREADS)
            d4[i] = s4[i];
    }

    // Resolve the 4 peer smem base addresses once.
    uint32_t mybase;
    asm("{ .reg .u64 t; cvta.to.shared.u64 t, %1; cvt.u32.u64 %0, t; }"
        : "=r"(mybase) : "l"(sval));
    uint32_t b0, b1, b2, b3;
    asm("mapa.shared::cluster.u32 %0, %1, %2;" : "=r"(b0) : "r"(mybase), "r"(0));
    asm("mapa.shared::cluster.u32 %0, %1, %2;" : "=r"(b1) : "r"(mybase), "r"(1));
    asm("mapa.shared::cluster.u32 %0, %1, %2;" : "=r"(b2) : "r"(mybase), "r"(2));
    asm("mapa.shared::cluster.u32 %0, %1, %2;" : "=r"(b3) : "r"(mybase), "r"(3));

    // All staging stores must be visible cluster-wide before any gather.
    asm volatile("barrier.cluster.arrive.aligned;" ::: "memory");
    asm volatile("barrier.cluster.wait.aligned;"   ::: "memory");

    const int warp = threadIdx.x >> 5;
    const int lane = threadIdx.x & 31;
    const int range_start = blockIdx.x * RANGE;
    const float wv = wptr[0];

    // Gather one child value from distributed smem.
    auto cgather = [&](int idx) -> float {
        const unsigned r   = (unsigned)idx / (unsigned)CHUNK;   // 0..3
        const unsigned off = (unsigned)idx - r * (unsigned)CHUNK;
        const uint32_t lo   = (r & 1u) ? b1 : b0;
        const uint32_t hi   = (r & 1u) ? b3 : b2;
        const uint32_t base = (r & 2u) ? hi : lo;
        float v;
        asm volatile("ld.shared::cluster.f32 %0, [%1];"
                     : "=f"(v) : "r"(base + off * 4u));
        return v;
    };

    for (int t = warp; t * 8 < RANGE; t += THREADS / 32) {
        const int node0 = range_start + t * 8;
        if (node0 >= N_NODES) break;

        const size_t ibase = (size_t)node0 * (N_CHILD / 4);
        const int4 cA = cidx[ibase + lane];
        const int4 cB = cidx[ibase + 32 + lane];

        float sA = (cgather(cA.x) + cgather(cA.y))
                 + (cgather(cA.z) + cgather(cA.w));
        float sB = (cgather(cB.x) + cgather(cB.y))
                 + (cgather(cB.z) + cgather(cB.w));

        sA += __shfl_down_sync(0xffffffffu, sA, 4);
        sB += __shfl_down_sync(0xffffffffu, sB, 4);
        sA += __shfl_down_sync(0xffffffffu, sA, 2);
        sB += __shfl_down_sync(0xffffffffu, sB, 2);
        sA += __shfl_down_sync(0xffffffffu, sA, 1);
        sB += __shfl_down_sync(0xffffffffu, sB, 1);

        if ((lane & 7) == 0) {
            const int g = lane >> 3;

            const int nodeA = node0 + g;
            const int fidA  = __ldg(fids + nodeA);
            const float xA  = wv * sA;
            float rA;
            if      (fidA == 0) rA = tanhf(xA);
            else if (fidA == 1) rA = 1.0f / (1.0f + expf(-xA));
            else if (fidA == 2) rA = fmaxf(xA, 0.0f);
            else                rA = xA;
            dst[nodeA] = rA;

            const int nodeB = node0 + 4 + g;
            const int fidB  = __ldg(fids + nodeB);
            const float xB  = wv * sB;
            float rB;
            if      (fidB == 0) rB = tanhf(xB);
            else if (fidB == 1) rB = 1.0f / (1.0f + expf(-xB));
            else if (fidB == 2) rB = fmaxf(xB, 0.0f);
            else                rB = xB;
            dst[nodeB] = rB;
        }
    }

    // No CTA may exit while cluster peers might still read its smem.
    asm volatile("barrier.cluster.arrive.aligned;" ::: "memory");
    asm volatile("barrier.cluster.wait.aligned;"   ::: "memory");
}

extern "C" void kernel_launch(void* const* d_in, const int* in_sizes, int n_in,
                              void* d_out, int out_size)
{
    const float* X    = (const float*)d_in[0];
    const float* w    = (const float*)d_in[1];
    const int*   cidx = (const int*)  d_in[2];  // [N_LAYERS, N_NODES, N_CHILD]
    const int*   fids = (const int*)  d_in[3];  // [N_LAYERS, N_NODES]
    float*       out  = (float*)d_out;

    float* bufA = nullptr;
    float* bufB = nullptr;
    cudaGetSymbolAddress((void**)&bufA, g_bufA);
    cudaGetSymbolAddress((void**)&bufB, g_bufB);

    const size_t SMEM_BYTES = (size_t)CHUNK * sizeof(float);  // 200KB
    cudaFuncSetAttribute(layer_cluster_kernel,
                         cudaFuncAttributeMaxDynamicSharedMemorySize,
                         (int)SMEM_BYTES);

    cudaLaunchConfig_t cfg = {};
    cfg.gridDim  = dim3(148, 1, 1);     // 37 clusters * 4 CTAs, one wave
    cfg.blockDim = dim3(THREADS, 1, 1);
    cfg.dynamicSmemBytes = SMEM_BYTES;
    cudaLaunchAttribute attrs[1];
    attrs[0].id = cudaLaunchAttributeClusterDimension;
    attrs[0].val.clusterDim = {CLUSTER, 1, 1};
    cfg.attrs = attrs;
    cfg.numAttrs = 1;

    // Ping-pong: layer i reads ins[i], writes outs[i] (always distinct).
    const float* ins[N_LAYERS]  = { X, bufA, bufB, bufA, bufB, bufA, bufB, bufA };
    float*       outs[N_LAYERS] = { bufA, bufB, bufA, bufB, bufA, bufB, bufA, out };

    for (int l = 0; l < N_LAYERS; l++) {
        const int4* layer_cidx =
            (const int4*)(cidx + (size_t)l * N_NODES * N_CHILD);
        const int* layer_fids = fids + (size_t)l * N_NODES;

        cudaLaunchKernelEx(&cfg, layer_cluster_kernel,
                           ins[l], outs[l], layer_cidx, layer_fids, w);
    }
}

// round 8
// speedup vs baseline: 2.6597x; 2.6597x over previous
#include <cuda_runtime.h>
#include <cstdint>

#define N_NODES    200000
#define N_CHILD    32
#define N_LAYERS   8
#define N_CHUNKS   4
#define CHUNK      50000          // floats per CTA chunk: 200KB smem
#define THREADS    1024
#define N_CLUSTERS 37
#define CLRANGE    5408           // nodes per cluster: 37*5408 >= 200000, %8==0
#define QUARTER    (CLRANGE / 4)  // 1352 nodes combined per CTA

// Ping-pong layer-value buffers (src/dst must stay distinct — no grid-wide
// sync inside a launch; same-buffer write races across clusters).
__device__ float g_bufA[N_NODES];
__device__ float g_bufB[N_NODES];

// Grid = 148 CTAs = 37 clusters of 4 (one wave, 1 CTA/SM).
// Cluster g owns nodes [g*CLRANGE, +CLRANGE). CTA rank c stages value chunk
// [c*CHUNK, +CHUNK) into smem, computes (via LOCAL predicated LDS — the fast
// crossbar path) the chunk-c partial sum for EVERY node in the cluster range
// into a smem partial array, then after one cluster barrier combines a
// quarter of the range by reading the 4 partial arrays via COALESCED
// ld.shared::cluster, applies w*sum + activation, writes dst.
// Indices are read with the proven R4 layout: 8 nodes/warp-task via two int4
// loads per lane; 8-lane shfl groups reduce each node's partial.
__global__ void __launch_bounds__(THREADS, 1) layer_fused_kernel(
    const float* __restrict__ src,     // previous layer values [N_NODES]
    float*       __restrict__ dst,     // this layer's outputs   [N_NODES]
    const int4*  __restrict__ cidx,    // this layer's indices as int4
    const int*   __restrict__ fids,    // this layer's fun_ids
    const float* __restrict__ wptr)
{
    extern __shared__ float smem_f[];
    float* sval = smem_f;              // CHUNK floats   (chunk values)
    float* spar = smem_f + CHUNK;      // CLRANGE floats (per-chunk partials)

    uint32_t rank;
    asm("mov.u32 %0, %%cluster_ctarank;" : "=r"(rank));
    const int cluster = blockIdx.x >> 2;          // matches rank grouping
    const int range_start = cluster * CLRANGE;
    const int cbase = (int)rank * CHUNK;

    // ---- Phase 1: stage this CTA's value chunk (coalesced float4) ----
    {
        const float4* s4 = (const float4*)(src + cbase);
        float4* d4 = (float4*)sval;
        for (int i = threadIdx.x; i < CHUNK / 4; i += THREADS)
            d4[i] = s4[i];
    }
    __syncthreads();

    // ---- Phase 2: chunk-c partial sums for all nodes in the range ----
    const int warp = threadIdx.x >> 5;
    const int lane = threadIdx.x & 31;

    for (int t = warp; t * 8 < CLRANGE; t += THREADS / 32) {
        const int node0 = range_start + t * 8;
        if (node0 >= N_NODES) break;

        const size_t ibase = (size_t)node0 * (N_CHILD / 4);
        const int4 cA = cidx[ibase + lane];
        const int4 cB = cidx[ibase + 32 + lane];

        float sA = 0.0f, sB = 0.0f;
        {
            unsigned r;
            r = (unsigned)(cA.x - cbase); if (r < CHUNK) sA += sval[r];
            r = (unsigned)(cA.y - cbase); if (r < CHUNK) sA += sval[r];
            r = (unsigned)(cA.z - cbase); if (r < CHUNK) sA += sval[r];
            r = (unsigned)(cA.w - cbase); if (r < CHUNK) sA += sval[r];
            r = (unsigned)(cB.x - cbase); if (r < CHUNK) sB += sval[r];
            r = (unsigned)(cB.y - cbase); if (r < CHUNK) sB += sval[r];
            r = (unsigned)(cB.z - cbase); if (r < CHUNK) sB += sval[r];
            r = (unsigned)(cB.w - cbase); if (r < CHUNK) sB += sval[r];
        }

        sA += __shfl_down_sync(0xffffffffu, sA, 4);
        sB += __shfl_down_sync(0xffffffffu, sB, 4);
        sA += __shfl_down_sync(0xffffffffu, sA, 2);
        sB += __shfl_down_sync(0xffffffffu, sB, 2);
        sA += __shfl_down_sync(0xffffffffu, sA, 1);
        sB += __shfl_down_sync(0xffffffffu, sB, 1);

        if ((lane & 7) == 0) {
            const int g = lane >> 3;
            spar[t * 8 + g]     = sA;
            spar[t * 8 + 4 + g] = sB;
        }
    }
    __syncthreads();

    // ---- Phase 3: cluster barrier (release local partials / acquire peers) ----
    asm volatile("barrier.cluster.arrive.aligned;" ::: "memory");
    asm volatile("barrier.cluster.wait.aligned;"   ::: "memory");

    // ---- Phase 4: combine a quarter of the range (coalesced DSMEM reads) ----
    {
        uint32_t pbase_local;
        asm("{ .reg .u64 t; cvta.to.shared.u64 t, %1; cvt.u32.u64 %0, t; }"
            : "=r"(pbase_local) : "l"(spar));
        uint32_t p0, p1, p2, p3;
        asm("mapa.shared::cluster.u32 %0, %1, %2;" : "=r"(p0) : "r"(pbase_local), "r"(0));
        asm("mapa.shared::cluster.u32 %0, %1, %2;" : "=r"(p1) : "r"(pbase_local), "r"(1));
        asm("mapa.shared::cluster.u32 %0, %1, %2;" : "=r"(p2) : "r"(pbase_local), "r"(2));
        asm("mapa.shared::cluster.u32 %0, %1, %2;" : "=r"(p3) : "r"(pbase_local), "r"(3));

        const float wv = wptr[0];
        const int qstart = range_start + (int)rank * QUARTER;

        for (int i = threadIdx.x; i < QUARTER; i += THREADS) {
            const int n = qstart + i;
            if (n >= N_NODES) break;
            const uint32_t off = (uint32_t)(n - range_start) * 4u;

            float v0, v1, v2, v3;
            asm volatile("ld.shared::cluster.f32 %0, [%1];" : "=f"(v0) : "r"(p0 + off));
            asm volatile("ld.shared::cluster.f32 %0, [%1];" : "=f"(v1) : "r"(p1 + off));
            asm volatile("ld.shared::cluster.f32 %0, [%1];" : "=f"(v2) : "r"(p2 + off));
            asm volatile("ld.shared::cluster.f32 %0, [%1];" : "=f"(v3) : "r"(p3 + off));

            const float s = (v0 + v1) + (v2 + v3);
            const float x = wv * s;
            const int fid = __ldg(fids + n);
            float rr;
            if      (fid == 0) rr = tanhf(x);
            else if (fid == 1) rr = 1.0f / (1.0f + expf(-x));
            else if (fid == 2) rr = fmaxf(x, 0.0f);
            else               rr = x;
            dst[n] = rr;
        }
    }

    // ---- Phase 5: no CTA exits while peers may still read its partials ----
    asm volatile("barrier.cluster.arrive.aligned;" ::: "memory");
    asm volatile("barrier.cluster.wait.aligned;"   ::: "memory");
}

extern "C" void kernel_launch(void* const* d_in, const int* in_sizes, int n_in,
                              void* d_out, int out_size)
{
    const float* X    = (const float*)d_in[0];
    const float* w    = (const float*)d_in[1];
    const int*   cidx = (const int*)  d_in[2];  // [N_LAYERS, N_NODES, N_CHILD]
    const int*   fids = (const int*)  d_in[3];  // [N_LAYERS, N_NODES]
    float*       out  = (float*)d_out;

    float* bufA = nullptr;
    float* bufB = nullptr;
    cudaGetSymbolAddress((void**)&bufA, g_bufA);
    cudaGetSymbolAddress((void**)&bufB, g_bufB);

    const size_t SMEM_BYTES = ((size_t)CHUNK + CLRANGE) * sizeof(float); // 221,632B
    cudaFuncSetAttribute(layer_fused_kernel,
                         cudaFuncAttributeMaxDynamicSharedMemorySize,
                         (int)SMEM_BYTES);

    cudaLaunchConfig_t cfg = {};
    cfg.gridDim  = dim3(N_CLUSTERS * N_CHUNKS, 1, 1);   // 148, one wave
    cfg.blockDim = dim3(THREADS, 1, 1);
    cfg.dynamicSmemBytes = SMEM_BYTES;
    cudaLaunchAttribute attrs[1];
    attrs[0].id = cudaLaunchAttributeClusterDimension;
    attrs[0].val.clusterDim = {N_CHUNKS, 1, 1};
    cfg.attrs = attrs;
    cfg.numAttrs = 1;

    // Ping-pong: layer i reads ins[i], writes outs[i] (always distinct).
    const float* ins[N_LAYERS]  = { X, bufA, bufB, bufA, bufB, bufA, bufB, bufA };
    float*       outs[N_LAYERS] = { bufA, bufB, bufA, bufB, bufA, bufB, bufA, out };

    for (int l = 0; l < N_LAYERS; l++) {
        const int4* layer_cidx =
            (const int4*)(cidx + (size_t)l * N_NODES * N_CHILD);
        const int* layer_fids = fids + (size_t)l * N_NODES;

        cudaLaunchKernelEx(&cfg, layer_fused_kernel,
                           ins[l], outs[l], layer_cidx, layer_fids, w);
    }
}

// round 9
// speedup vs baseline: 4.5249x; 1.7013x over previous
#include <cuda_runtime.h>
#include <cstdint>

#define N_NODES    200000
#define N_CHILD    32
#define N_LAYERS   8
#define N_CHUNKS   4
#define CHUNK      50000          // floats per chunk: 200KB smem; 4*50000=200000
#define N_RANGES   37
#define RANGE_SZ   5408           // 37*5408 >= 200000, multiple of 8
#define THREADS    1024
#define N_WARPS    (THREADS / 32)

// Ping-pong layer-value buffers (src/dst distinct — no grid sync in a launch).
__device__ float g_bufA[N_NODES];
__device__ float g_bufB[N_NODES];
__device__ float g_partial[N_CHUNKS][N_NODES];   // per-chunk partial sums
// Monotonic arrival counters (replay-safe via mod-4; zero-init once at load).
__device__ unsigned g_arrive[N_RANGES];

// Grid = 37 ranges x 4 chunks = 148 blocks, free scheduling (NO clusters).
// Block (range,chunk): stages its 50K-float chunk to smem, computes chunk-c
// partial sums for all nodes of its range via predicated LDS (fast crossbar),
// stores partials to gmem, then fence+atomicAdd on the range's counter.
// The 4th arriver combines the range: sum 4 partials (L2-hot), w*sum,
// activation, write dst. Values are deterministic; only the executing SM
// varies. Combine overlaps other ranges' gather work.
__global__ void __launch_bounds__(THREADS, 1) layer_kernel(
    const float* __restrict__ src,     // previous layer values [N_NODES]
    float*       __restrict__ dst,     // this layer's outputs   [N_NODES]
    const int4*  __restrict__ cidx,    // this layer's indices as int4
    const int*   __restrict__ fids,    // this layer's fun_ids
    const float* __restrict__ wptr)
{
    extern __shared__ float sval[];    // CHUNK floats

    const int chunk = blockIdx.x & (N_CHUNKS - 1);
    const int range = blockIdx.x >> 2;
    const int cbase = chunk * CHUNK;
    const int range_start = range * RANGE_SZ;

    // ---- Phase 1: stage chunk (coalesced float4; src is L2-resident) ----
    {
        const float4* s4 = (const float4*)(src + cbase);
        float4* d4 = (float4*)sval;
        for (int i = threadIdx.x; i < CHUNK / 4; i += THREADS)
            d4[i] = s4[i];
    }
    __syncthreads();

    // ---- Phase 2: partial sums, with index prefetch (double-buffered) ----
    const int warp = threadIdx.x >> 5;
    const int lane = threadIdx.x & 31;

    int t = warp;
    bool valid = (t * 8 < RANGE_SZ) && (range_start + t * 8 < N_NODES);
    int4 cA, cB;
    if (valid) {
        const size_t ib = (size_t)(range_start + t * 8) * (N_CHILD / 4);
        cA = cidx[ib + lane];
        cB = cidx[ib + 32 + lane];
    }

    while (valid) {
        // Prefetch next task's indices before touching smem.
        const int tn = t + N_WARPS;
        const bool nvalid = (tn * 8 < RANGE_SZ) &&
                            (range_start + tn * 8 < N_NODES);
        int4 nA, nB;
        if (nvalid) {
            const size_t ib = (size_t)(range_start + tn * 8) * (N_CHILD / 4);
            nA = cidx[ib + lane];
            nB = cidx[ib + 32 + lane];
        }

        float sA = 0.0f, sB = 0.0f;
        {
            unsigned r;
            r = (unsigned)(cA.x - cbase); if (r < CHUNK) sA += sval[r];
            r = (unsigned)(cA.y - cbase); if (r < CHUNK) sA += sval[r];
            r = (unsigned)(cA.z - cbase); if (r < CHUNK) sA += sval[r];
            r = (unsigned)(cA.w - cbase); if (r < CHUNK) sA += sval[r];
            r = (unsigned)(cB.x - cbase); if (r < CHUNK) sB += sval[r];
            r = (unsigned)(cB.y - cbase); if (r < CHUNK) sB += sval[r];
            r = (unsigned)(cB.z - cbase); if (r < CHUNK) sB += sval[r];
            r = (unsigned)(cB.w - cbase); if (r < CHUNK) sB += sval[r];
        }

        sA += __shfl_down_sync(0xffffffffu, sA, 4);
        sB += __shfl_down_sync(0xffffffffu, sB, 4);
        sA += __shfl_down_sync(0xffffffffu, sA, 2);
        sB += __shfl_down_sync(0xffffffffu, sB, 2);
        sA += __shfl_down_sync(0xffffffffu, sA, 1);
        sB += __shfl_down_sync(0xffffffffu, sB, 1);

        if ((lane & 7) == 0) {
            const int g = lane >> 3;
            const int node0 = range_start + t * 8;
            g_partial[chunk][node0 + g]     = sA;
            g_partial[chunk][node0 + 4 + g] = sB;
        }

        t = tn; valid = nvalid; cA = nA; cB = nB;
    }

    // ---- Phase 3: publish partials, count arrivals ----
    __threadfence();        // each thread's partial stores visible gpu-wide
    __syncthreads();        // all threads' fences done before the arrival

    __shared__ int s_combine;
    if (threadIdx.x == 0) {
        const unsigned old = atomicAdd(&g_arrive[range], 1u);
        s_combine = ((old & 3u) == 3u) ? 1 : 0;
    }
    __syncthreads();

    // ---- Phase 4: 4th arriver combines this range ----
    if (s_combine) {
        __threadfence();    // acquire: see peers' partial stores
        const float wv = wptr[0];
        for (int i = threadIdx.x; i < RANGE_SZ; i += THREADS) {
            const int n = range_start + i;
            if (n >= N_NODES) break;
            const float s = (g_partial[0][n] + g_partial[1][n])
                          + (g_partial[2][n] + g_partial[3][n]);
            const float x = wv * s;
            const int fid = __ldg(fids + n);
            float r;
            if      (fid == 0) r = tanhf(x);
            else if (fid == 1) r = 1.0f / (1.0f + expf(-x));
            else if (fid == 2) r = fmaxf(x, 0.0f);
            else               r = x;
            dst[n] = r;
        }
    }
}

extern "C" void kernel_launch(void* const* d_in, const int* in_sizes, int n_in,
                              void* d_out, int out_size)
{
    const float* X    = (const float*)d_in[0];
    const float* w    = (const float*)d_in[1];
    const int*   cidx = (const int*)  d_in[2];  // [N_LAYERS, N_NODES, N_CHILD]
    const int*   fids = (const int*)  d_in[3];  // [N_LAYERS, N_NODES]
    float*       out  = (float*)d_out;

    float* bufA = nullptr;
    float* bufB = nullptr;
    cudaGetSymbolAddress((void**)&bufA, g_bufA);
    cudaGetSymbolAddress((void**)&bufB, g_bufB);

    const size_t SMEM_BYTES = (size_t)CHUNK * sizeof(float);  // 200KB
    cudaFuncSetAttribute(layer_kernel,
                         cudaFuncAttributeMaxDynamicSharedMemorySize,
                         (int)SMEM_BYTES);

    // Ping-pong: layer i reads ins[i], writes outs[i] (always distinct).
    const float* ins[N_LAYERS]  = { X, bufA, bufB, bufA, bufB, bufA, bufB, bufA };
    float*       outs[N_LAYERS] = { bufA, bufB, bufA, bufB, bufA, bufB, bufA, out };

    const int grid = N_RANGES * N_CHUNKS;   // 148 blocks, one wave

    for (int l = 0; l < N_LAYERS; l++) {
        const int4* layer_cidx =
            (const int4*)(cidx + (size_t)l * N_NODES * N_CHILD);
        const int* layer_fids = fids + (size_t)l * N_NODES;

        layer_kernel<<<grid, THREADS, SMEM_BYTES>>>(
            ins[l], outs[l], layer_cidx, layer_fids, w);
    }
}